// round 1
// baseline (speedup 1.0000x reference)
#include <cuda_runtime.h>
#include <math.h>

// Problem constants
#define NS     64      // spins
#define HID    20      // hidden channels per spin
#define HDIM   1280    // NS*HID
#define BATCH  16384
// Kernel config
#define MROWS  8                      // batch rows per CTA
#define NQ     4                      // K-split per output
#define NOUT   (HID*MROWS)            // 160 outputs per layer per CTA
#define THREADS (NQ*NOUT)             // 640 threads = 20 warps (5/SMSP, balanced)
#define HSTR   1284                   // padded h row stride (floats) -> conflict-free LDS.128
#define SSTR   65                     // padded stride for sample / pre6 rows

// Spin-major re-laid-out weights (prep kernels fill these; ~26MB, lives in L2)
__device__ float g_Wp[4][HDIM*HDIM];    // layers 2..5: [so*20+co][si*20+ci]
__device__ float g_W1p[HDIM*NS];        // fc1:        [so*20+co][j]
__device__ float g_W6p[NS*NS*HID];      // fc6 scatter: [(si*64+j)*20 + ci]

__global__ void prep_big(const float* __restrict__ W2, const float* __restrict__ W3,
                         const float* __restrict__ W4, const float* __restrict__ W5)
{
    int l = blockIdx.y;
    const float* W = (l == 0) ? W2 : (l == 1) ? W3 : (l == 2) ? W4 : W5;
    int idx = blockIdx.x * blockDim.x + threadIdx.x;
    if (idx >= HDIM * HDIM) return;
    int a = idx / HDIM, b = idx - a * HDIM;
    int so = a / HID, co = a - so * HID;
    int si = b / HID, ci = b - si * HID;
    // masked entries (si > so) are never read -> no masking needed
    g_Wp[l][idx] = W[(size_t)(co * NS + so) * HDIM + (ci * NS + si)];
}

__global__ void prep_small(const float* __restrict__ W1, const float* __restrict__ W6)
{
    int idx = blockIdx.x * blockDim.x + threadIdx.x;
    if (idx < HDIM * NS) {               // 81920
        int a = idx / NS, j = idx - a * NS;
        int so = a / HID, co = a - so * HID;
        g_W1p[idx] = W1[(size_t)(co * NS + so) * NS + j];
    }
    if (idx < NS * NS * HID) {           // 81920
        int ci = idx % HID;
        int t  = idx / HID;
        int j  = t % NS;
        int si = t / NS;
        g_W6p[idx] = W6[(size_t)j * HDIM + ci * NS + si];
    }
}

__device__ __forceinline__ float sigmoidf(float x) { return 1.0f / (1.0f + expf(-x)); }

// Persistent per-CTA autoregressive kernel. Each CTA owns MROWS batch rows and
// runs all 64 sampling steps independently (batch rows are independent).
// SMEM state per CTA: h1..h4 [MROWS][HSTR] fp32, sample s, fc6 accumulator pre6.
__global__ void __launch_bounds__(THREADS, 1)
net_kernel(const float* __restrict__ u, float* __restrict__ out)
{
    extern __shared__ float sm[];
    float* hbuf = sm;                          // 4 * MROWS * HSTR   (h1..h4)
    float* svec = hbuf + 4 * MROWS * HSTR;     // MROWS * SSTR       (sample, +/-1)
    float* pre6 = svec + MROWS * SSTR;         // MROWS * SSTR       (fc6 pre-acts)
    float* h5b  = pre6 + MROWS * SSTR;         // MROWS * HID        (h5 of spin i)
    float* part = h5b  + MROWS * HID;          // (NQ-1) * NOUT      (K-split partials)

    const int tid = threadIdx.x;
    const int r   = tid & (MROWS - 1);         // batch row within CTA
    const int c   = (tid >> 3) % HID;          // output channel
    const int q   = tid / NOUT;                // K-quarter
    const int o   = tid % NOUT;                // output index (c*8 + r)

    // init fc6 accumulators
    for (int k = tid; k < MROWS * SSTR; k += THREADS) pre6[k] = 0.0f;
    __syncthreads();

    for (int i = 0; i < NS; ++i) {
        // ---- Phase A: h1 for spin i (exclusive: uses inputs j < i, all final) ----
        if (q == 0) {
            const float* w  = g_W1p + (size_t)(i * HID + c) * NS;
            const float* sr = svec + r * SSTR;
            float acc = 0.0f;
            for (int j = 0; j < i; ++j) acc = fmaf(w[j], sr[j], acc);
            hbuf[r * HSTR + i * HID + c] = sigmoidf(acc);   // level 0 = h1
        }
        __syncthreads();

        // ---- Phases B..E: layers 2..5, spin-i channels only. K = (i+1)*20 ----
        const int K4 = (i + 1) * 5;            // in float4 units
        const int kb = (K4 * q) >> 2;
        const int ke = (K4 * (q + 1)) >> 2;

        for (int l = 0; l < 4; ++l) {
            const float4* w4 = (const float4*)(g_Wp[l] + (size_t)(i * HID + c) * HDIM);
            const float4* x4 = (const float4*)(hbuf + (size_t)l * MROWS * HSTR + r * HSTR);
            float a0 = 0.f, a1 = 0.f, a2 = 0.f, a3 = 0.f;
            int k = kb;
            for (; k + 4 <= ke; k += 4) {
                float4 wa = w4[k+0], wb = w4[k+1], wc = w4[k+2], wd = w4[k+3];
                float4 xa = x4[k+0], xb = x4[k+1], xc = x4[k+2], xd = x4[k+3];
                a0 = fmaf(wa.x, xa.x, a0); a1 = fmaf(wa.y, xa.y, a1);
                a2 = fmaf(wa.z, xa.z, a2); a3 = fmaf(wa.w, xa.w, a3);
                a0 = fmaf(wb.x, xb.x, a0); a1 = fmaf(wb.y, xb.y, a1);
                a2 = fmaf(wb.z, xb.z, a2); a3 = fmaf(wb.w, xb.w, a3);
                a0 = fmaf(wc.x, xc.x, a0); a1 = fmaf(wc.y, xc.y, a1);
                a2 = fmaf(wc.z, xc.z, a2); a3 = fmaf(wc.w, xc.w, a3);
                a0 = fmaf(wd.x, xd.x, a0); a1 = fmaf(wd.y, xd.y, a1);
                a2 = fmaf(wd.z, xd.z, a2); a3 = fmaf(wd.w, xd.w, a3);
            }
            for (; k < ke; ++k) {
                float4 wa = w4[k], xa = x4[k];
                a0 = fmaf(wa.x, xa.x, a0); a1 = fmaf(wa.y, xa.y, a1);
                a2 = fmaf(wa.z, xa.z, a2); a3 = fmaf(wa.w, xa.w, a3);
            }
            float partial = (a0 + a1) + (a2 + a3);
            if (q > 0) part[(q - 1) * NOUT + o] = partial;
            __syncthreads();
            if (q == 0) {
                float tot = partial + part[o] + part[NOUT + o] + part[2 * NOUT + o];
                float val = sigmoidf(tot);
                if (l < 3) hbuf[(size_t)(l + 1) * MROWS * HSTR + r * HSTR + i * HID + c] = val;
                else       h5b[r * HID + c] = val;
            }
            __syncthreads();
        }

        // ---- Phase F: scatter spin-i h5 into fc6 pre-activations for all j >= i ----
        {
            const int cnt = (NS - i) * MROWS;
            for (int idx = tid; idx < cnt; idx += THREADS) {
                int rr = idx & (MROWS - 1);
                int j  = i + (idx >> 3);
                const float* w  = g_W6p + (size_t)(i * NS + j) * HID;
                const float* hv = h5b + rr * HID;
                float acc = 0.0f;
                #pragma unroll
                for (int cc = 0; cc < HID; ++cc) acc = fmaf(w[cc], hv[cc], acc);
                pre6[rr * SSTR + j] += acc;
            }
        }
        __syncthreads();

        // ---- Sample: x_i = sigmoid(pre6[:,i]) is ALSO the final output column i ----
        if (tid < MROWS) {
            int rg = blockIdx.x * MROWS + tid;
            float x = sigmoidf(pre6[tid * SSTR + i]);
            out[(size_t)rg * NS + i] = x;
            svec[tid * SSTR + i] = (x >= u[(size_t)i * BATCH + rg]) ? 1.0f : -1.0f;
        }
        __syncthreads();
    }
}

extern "C" void kernel_launch(void* const* d_in, const int* in_sizes, int n_in,
                              void* d_out, int out_size)
{
    (void)in_sizes; (void)n_in; (void)out_size;
    // metadata order: sample, u, W1, W2, W3, W4, W5, W6
    const float* u  = (const float*)d_in[1];
    const float* W1 = (const float*)d_in[2];
    const float* W2 = (const float*)d_in[3];
    const float* W3 = (const float*)d_in[4];
    const float* W4 = (const float*)d_in[5];
    const float* W5 = (const float*)d_in[6];
    const float* W6 = (const float*)d_in[7];
    float* out = (float*)d_out;

    // Weight re-layout (runs inside the graph each replay; ~tens of us)
    dim3 gb((HDIM * HDIM + 255) / 256, 4);
    prep_big<<<gb, 256>>>(W2, W3, W4, W5);
    prep_small<<<(HDIM * NS + 255) / 256, 256>>>(W1, W6);

    const int smem_bytes = (4 * MROWS * HSTR + 2 * MROWS * SSTR + MROWS * HID
                            + (NQ - 1) * NOUT) * (int)sizeof(float);
    cudaFuncSetAttribute(net_kernel, cudaFuncAttributeMaxDynamicSharedMemorySize, smem_bytes);
    net_kernel<<<BATCH / MROWS, THREADS, smem_bytes>>>(u, out);
}

// round 2
// speedup vs baseline: 1.7089x; 1.7089x over previous
#include <cuda_runtime.h>
#include <math.h>

#define NS     64
#define HID    20
#define HDIM   1280
#define BATCH  16384
#define MROWS  8
#define T      640            // threads per CTA (20 warps)

// Scatter-major weights:
//  g_Ws[l]: for each si, slab of (64-si) x 20 x 20: [so-si][c][ci]; diag (so=si) first.
//  g_W1s : for each si, (63-si) x 20: [so-si-1][c]          (fc1, exclusive)
//  g_W6s : for each si, (64-si) x 20: [so-si][ci]; diag first.
#define LVL_STRIDE 832000      // 2080*400 floats per level
__device__ float g_Ws[4 * LVL_STRIDE];   // 13.3 MB
__device__ float g_W1s[2016 * 20];
__device__ float g_W6s[2080 * 20];

__device__ __forceinline__ int slab_off(int si)  { return 64 * si - (si * (si - 1)) / 2; }  // Σ_{k<si}(64-k)
__device__ __forceinline__ int slab_off1(int si) { return 63 * si - (si * (si - 1)) / 2; }  // Σ_{k<si}(63-k)

__global__ void prep_scatter(const float* __restrict__ W1, const float* __restrict__ W2,
                             const float* __restrict__ W3, const float* __restrict__ W4,
                             const float* __restrict__ W5, const float* __restrict__ W6)
{
    const int si = blockIdx.x;
    const int what = blockIdx.y;           // 0..3 = fc2..fc5, 4 = fc1, 5 = fc6
    const int nso = NS - si;
    if (what < 4) {
        const float* W = (what == 0) ? W2 : (what == 1) ? W3 : (what == 2) ? W4 : W5;
        float* dst = g_Ws + (size_t)what * LVL_STRIDE + (size_t)slab_off(si) * 400;
        const int cnt = nso * 400;
        for (int t = threadIdx.x; t < cnt; t += blockDim.x) {
            int dso = t / 400, rem = t - dso * 400;
            int c = rem / 20, ci = rem - c * 20;
            int so = si + dso;
            dst[t] = W[(size_t)(c * NS + so) * HDIM + ci * NS + si];
        }
    } else if (what == 4) {
        float* dst = g_W1s + (size_t)slab_off1(si) * 20;
        const int cnt = (63 - si) * 20;
        for (int t = threadIdx.x; t < cnt; t += blockDim.x) {
            int dso = t / 20, c = t - dso * 20;
            int so = si + 1 + dso;
            dst[t] = W1[(size_t)(c * NS + so) * NS + si];
        }
    } else {
        float* dst = g_W6s + (size_t)slab_off(si) * 20;
        const int cnt = nso * 20;
        for (int t = threadIdx.x; t < cnt; t += blockDim.x) {
            int dso = t / 20, ci = t - dso * 20;
            int so = si + dso;
            dst[t] = W6[(size_t)so * HDIM + ci * NS + si];
        }
    }
}

// ---- packed f32x2 helpers ----
__device__ __forceinline__ unsigned long long ffma2(unsigned long long a, unsigned long long b,
                                                    unsigned long long c)
{
    unsigned long long d;
    asm("fma.rn.f32x2 %0, %1, %2, %3;" : "=l"(d) : "l"(a), "l"(b), "l"(c));
    return d;
}
__device__ __forceinline__ unsigned long long pack2(float lo, float hi)
{
    unsigned long long v;
    asm("mov.b64 %0, {%1, %2};" : "=l"(v) : "f"(lo), "f"(hi));
    return v;
}
__device__ __forceinline__ float hsum2(unsigned long long v)
{
    float lo, hi;
    asm("mov.b64 {%0, %1}, %2;" : "=f"(lo), "=f"(hi) : "l"(v));
    return lo + hi;
}
__device__ __forceinline__ float sigmoidf(float x) { return 1.0f / (1.0f + expf(-x)); }

// 20-float dot (10 packed FFMA2) against broadcast h row, acc seeded with pre value.
__device__ __forceinline__ float dot20(const ulonglong2* wp, const ulonglong2* hp, float pre)
{
    ulonglong2 w0 = wp[0], w1 = wp[1], w2 = wp[2], w3 = wp[3], w4 = wp[4];
    ulonglong2 h0 = hp[0], h1 = hp[1], h2 = hp[2], h3 = hp[3], h4 = hp[4];
    unsigned long long acc = pack2(pre, 0.0f);
    acc = ffma2(w0.x, h0.x, acc); acc = ffma2(w0.y, h0.y, acc);
    acc = ffma2(w1.x, h1.x, acc); acc = ffma2(w1.y, h1.y, acc);
    acc = ffma2(w2.x, h2.x, acc); acc = ffma2(w2.y, h2.y, acc);
    acc = ffma2(w3.x, h3.x, acc); acc = ffma2(w3.y, h3.y, acc);
    acc = ffma2(w4.x, h4.x, acc); acc = ffma2(w4.y, h4.y, acc);
    return hsum2(acc);
}

// Persistent per-CTA autoregressive kernel: 8 batch rows per CTA, scatter-form.
__global__ void __launch_bounds__(T, 1)
net_kernel(const float* __restrict__ u, float* __restrict__ out)
{
    extern __shared__ float sm[];
    float* pre  = sm;                       // [5][8][1280]  pre1..pre5 accumulators
    float* pre6 = pre + 5 * MROWS * HDIM;   // [8][64]
    float* hbt  = pre6 + MROWS * NS;        // [5][8][20]    h1..h5 of current spin
    float* usm  = hbt + 5 * MROWS * HID;    // [8][64]
    float* osm  = usm + MROWS * NS;         // [8][64]
    float* wd   = osm + MROWS * NS;         // [2024]        diag weights (5*400 + 20)
    float* scur = wd + 2024;                // [8]

    const int tid = threadIdx.x;

    // init accumulators (pre, pre6 contiguous), stage u, prefetch step-0 diag weights
    for (int k = tid; k < 5 * MROWS * HDIM + MROWS * NS; k += T) pre[k] = 0.0f;
    if (tid < 512) {
        int i = tid >> 3, r = tid & 7;
        usm[r * NS + i] = u[(size_t)i * BATCH + (size_t)blockIdx.x * MROWS + r];
    }
    for (int k = tid; k < 2020; k += T) {
        if (k < 2000) { int l = k / 400; wd[k] = g_Ws[(size_t)l * LVL_STRIDE + (k - l * 400)]; }
        else          wd[k] = g_W6s[k - 2000];
    }
    __syncthreads();

    for (int i = 0; i < NS; ++i) {
        // ===== diagonal chain (critical path, 160 threads) =====
        if (tid < 160) {
            int r = tid / 20, c = tid - (tid / 20) * 20;
            hbt[r * 20 + c] = sigmoidf(pre[r * HDIM + i * HID + c]);   // h1 = σ(pre1)
        }
        __syncthreads();
        #pragma unroll 1
        for (int lv = 0; lv < 4; ++lv) {
            if (tid < 160) {
                int r = tid / 20, c = tid - (tid / 20) * 20;
                float acc = pre[((lv + 1) * MROWS + r) * HDIM + i * HID + c];
                const float* w  = wd + lv * 400 + c * 20;
                const float* hh = hbt + lv * 160 + r * 20;
                #pragma unroll
                for (int ci = 0; ci < 20; ++ci) acc = fmaf(w[ci], hh[ci], acc);
                hbt[(lv + 1) * 160 + r * 20 + c] = sigmoidf(acc);
            }
            __syncthreads();
        }
        if (tid < MROWS) {   // fc6 diag + sample
            int r = tid;
            float acc = pre6[r * NS + i];
            const float* w  = wd + 2000;
            const float* hh = hbt + 4 * 160 + r * 20;
            #pragma unroll
            for (int ci = 0; ci < 20; ++ci) acc = fmaf(w[ci], hh[ci], acc);
            float x = sigmoidf(acc);
            osm[r * NS + i] = x;
            scur[r] = (x >= usm[r * NS + i]) ? 1.0f : -1.0f;
        }
        __syncthreads();

        // ===== scatter phase (bulk, off critical path) =====
        if (i < 63) {
            const int nso = 63 - i;
            const int n20 = nso * 20;
            const size_t off = (size_t)slab_off(i) * 400;

            // fc2..fc5: pre[l+1][r][tgt] += <Wl[i][so][c][:], h_{l+1}[r][:]>
            #pragma unroll 1
            for (int l = 0; l < 4; ++l) {
                const float* wbase = g_Ws + (size_t)l * LVL_STRIDE + off + 400; // skip diag
                float* prl = pre + (size_t)(l + 1) * MROWS * HDIM;
                const float* hl = hbt + l * 160;
                for (int j = tid; j < n20; j += T) {
                    const ulonglong2* wp = (const ulonglong2*)(wbase + (size_t)j * 20);
                    const int tgt = (i + 1) * HID + j;    // (so-i-1)*20 + c == j
                    #pragma unroll
                    for (int r = 0; r < MROWS; ++r) {
                        float* dst = prl + r * HDIM + tgt;
                        *dst = dot20(wp, (const ulonglong2*)(hl + r * 20), *dst);
                    }
                }
            }
            // fc1: pre1[r][tgt] += W1[so,c][i] * s[i]
            {
                const float* wb = g_W1s + (size_t)slab_off1(i) * 20;
                float s0 = scur[0], s1 = scur[1], s2 = scur[2], s3 = scur[3];
                float s4 = scur[4], s5 = scur[5], s6 = scur[6], s7 = scur[7];
                for (int j = tid; j < n20; j += T) {
                    float w = wb[j];
                    float* dst = pre + (i + 1) * HID + j;
                    dst[0 * HDIM] += w * s0;  dst[1 * HDIM] += w * s1;
                    dst[2 * HDIM] += w * s2;  dst[3 * HDIM] += w * s3;
                    dst[4 * HDIM] += w * s4;  dst[5 * HDIM] += w * s5;
                    dst[6 * HDIM] += w * s6;  dst[7 * HDIM] += w * s7;
                }
            }
            // fc6: pre6[r][so] += <W6[so][i*20+:], h5[r][:]>
            {
                const float* wb = g_W6s + (size_t)slab_off(i) * 20 + 20;  // skip diag
                const float* h5 = hbt + 4 * 160;
                for (int j = tid; j < nso; j += T) {
                    const ulonglong2* wp = (const ulonglong2*)(wb + (size_t)j * 20);
                    #pragma unroll
                    for (int r = 0; r < MROWS; ++r) {
                        float* dst = pre6 + r * NS + (i + 1 + j);
                        *dst = dot20(wp, (const ulonglong2*)(h5 + r * 20), *dst);
                    }
                }
            }
            // prefetch next step's diag weights into smem (overlaps scatter)
            {
                const size_t noff = (size_t)slab_off(i + 1);
                for (int k = tid; k < 2020; k += T) {
                    if (k < 2000) {
                        int l = k / 400;
                        wd[k] = g_Ws[(size_t)l * LVL_STRIDE + noff * 400 + (k - l * 400)];
                    } else {
                        wd[k] = g_W6s[noff * 20 + (k - 2000)];
                    }
                }
            }
        }
        __syncthreads();
    }

    // coalesced output write
    if (tid < 512)
        out[(size_t)blockIdx.x * 512 + tid] = osm[tid];
}

extern "C" void kernel_launch(void* const* d_in, const int* in_sizes, int n_in,
                              void* d_out, int out_size)
{
    (void)in_sizes; (void)n_in; (void)out_size;
    const float* u  = (const float*)d_in[1];
    const float* W1 = (const float*)d_in[2];
    const float* W2 = (const float*)d_in[3];
    const float* W3 = (const float*)d_in[4];
    const float* W4 = (const float*)d_in[5];
    const float* W5 = (const float*)d_in[6];
    const float* W6 = (const float*)d_in[7];
    float* out = (float*)d_out;

    dim3 pg(64, 6);
    prep_scatter<<<pg, 256>>>(W1, W2, W3, W4, W5, W6);

    const int smem_bytes = (5 * MROWS * HDIM + MROWS * NS      // pre, pre6
                            + 5 * MROWS * HID                  // h
                            + 2 * MROWS * NS                   // u, out
                            + 2024 + 8) * (int)sizeof(float);  // wd, scur
    cudaFuncSetAttribute(net_kernel, cudaFuncAttributeMaxDynamicSharedMemorySize, smem_bytes);
    net_kernel<<<BATCH / MROWS, T, smem_bytes>>>(u, out);
}

// round 3
// speedup vs baseline: 1.7586x; 1.0291x over previous
#include <cuda_runtime.h>
#include <math.h>

#define NS     64
#define HID    20
#define HDIM   1280
#define BATCH  16384
#define MROWS  8
#define T      640
#define PSTR   1284            // padded pre row stride (words): conflict-free RMW
#define P6STR  68
#define LVL    806400          // 2016*400 floats per level (scatter slabs, no diag)

// Scatter weights, chunk-major per (level, si) slab:
//   slab for si: nt=(63-si)*20 targets; element (k,j) at float offset (k*nt+j)*4,
//   holding W[(c*64+so)*1280 + (4k+m)*64 + si], j=(so-si-1)*20+c.
__device__ float g_Ws4[4 * LVL];          // fc2..fc5, 12.9 MB
__device__ float g_W1s[2016 * 20];        // fc1 (rank-1 scatter)
__device__ float g_W6s[2016 * 20];        // fc6 chunk-major: (k,t) at (k*nso1+t)*4
__device__ float g_Wd [64 * 2020];        // diag weights per si: 4*400 + 20 (fc6)

__device__ __forceinline__ int slab_off1(int si) { return 63 * si - (si * (si - 1)) / 2; }

__global__ void prep_scatter(const float* __restrict__ W1, const float* __restrict__ W2,
                             const float* __restrict__ W3, const float* __restrict__ W4,
                             const float* __restrict__ W5, const float* __restrict__ W6)
{
    const int si = blockIdx.x, what = blockIdx.y;
    const int nso1 = 63 - si;
    const int nt = nso1 * 20;
    if (what < 4) {
        const float* W = (what == 0) ? W2 : (what == 1) ? W3 : (what == 2) ? W4 : W5;
        float* dst = g_Ws4 + (size_t)what * LVL + (size_t)slab_off1(si) * 400;
        const int cnt = nso1 * 400;
        for (int t = threadIdx.x; t < cnt; t += blockDim.x) {
            int m = t & 3, q = t >> 2;
            int j = q % nt, k = q / nt;
            int so = si + 1 + j / 20, c = j % 20, ci = 4 * k + m;
            dst[t] = W[(size_t)(c * NS + so) * HDIM + ci * NS + si];
        }
    } else if (what == 4) {
        float* d1 = g_W1s + (size_t)slab_off1(si) * 20;
        for (int t = threadIdx.x; t < nt; t += blockDim.x) {
            int so = si + 1 + t / 20, c = t % 20;
            d1[t] = W1[(size_t)(c * NS + so) * NS + si];
        }
        float* dd = g_Wd + (size_t)si * 2020;
        for (int t = threadIdx.x; t < 2020; t += blockDim.x) {
            if (t < 1600) {
                int l = t / 400, rem = t - l * 400;
                int c = rem / 20, ci = rem - c * 20;
                const float* W = (l == 0) ? W2 : (l == 1) ? W3 : (l == 2) ? W4 : W5;
                dd[t] = W[(size_t)(c * NS + si) * HDIM + ci * NS + si];
            } else if (t < 2000) {
                dd[t] = 0.0f;  // unused pad (kept 5*400 layout, only 4 levels)
            } else {
                dd[t] = W6[(size_t)si * HDIM + (t - 2000) * NS + si];
            }
        }
    } else {
        float* d6 = g_W6s + (size_t)slab_off1(si) * 20;
        for (int t = threadIdx.x; t < nt; t += blockDim.x) {
            int m = t & 3, q = t >> 2;
            int tt = q % nso1, k = q / nso1;
            int so = si + 1 + tt, ci = 4 * k + m;
            d6[t] = W6[(size_t)so * HDIM + ci * NS + si];
        }
    }
}

// fix: diag levels are fc2..fc5 at [l*400] for l in 0..3 (1600 floats), fc6 at 2000.
// (slots 1600..1999 are padding)

// ---- packed f32x2 helpers ----
__device__ __forceinline__ unsigned long long ffma2(unsigned long long a, unsigned long long b,
                                                    unsigned long long c)
{
    unsigned long long d;
    asm("fma.rn.f32x2 %0, %1, %2, %3;" : "=l"(d) : "l"(a), "l"(b), "l"(c));
    return d;
}
__device__ __forceinline__ unsigned long long pack2(float lo, float hi)
{
    unsigned long long v;
    asm("mov.b64 %0, {%1, %2};" : "=l"(v) : "f"(lo), "f"(hi));
    return v;
}
__device__ __forceinline__ float hsum2(unsigned long long v)
{
    float lo, hi;
    asm("mov.b64 {%0, %1}, %2;" : "=f"(lo), "=f"(hi) : "l"(v));
    return lo + hi;
}
__device__ __forceinline__ float sigmoidf(float x) { return 1.0f / (1.0f + expf(-x)); }

__global__ void __launch_bounds__(T, 1)
net_kernel(const float* __restrict__ u, float* __restrict__ out)
{
    extern __shared__ float sm[];
    float* pre  = sm;                       // [5][8][PSTR]  (level 0 = pre1)
    float* pre6 = pre + 5 * MROWS * PSTR;   // [8][P6STR]
    float* hbt  = pre6 + MROWS * P6STR;     // [5][160]
    float* usm  = hbt + 5 * 160;            // [512]
    float* osm  = usm + 512;                // [512]
    float* wd   = osm + 512;                // [2020]
    float* scur = wd + 2020;                // [8]

    const int tid = threadIdx.x;
    const int pair = tid & 3, jj = tid >> 2;     // jj in 0..159
    const int r0 = 2 * pair, r1 = r0 + 1;

    for (int k = tid; k < 5 * MROWS * PSTR; k += T) pre[k] = 0.0f;
    for (int k = tid; k < MROWS * P6STR; k += T) pre6[k] = 0.0f;
    if (tid < 512) {
        int i = tid >> 3, r = tid & 7;
        usm[r * NS + i] = u[(size_t)i * BATCH + (size_t)blockIdx.x * MROWS + r];
    }
    for (int k = tid; k < 2020; k += T) wd[k] = g_Wd[k];
    __syncthreads();

    for (int i = 0; i < NS; ++i) {
        // ===== diagonal chain: warps 0..4 (160 threads), named barriers =====
        if (tid < 160) {
            const int r = tid / 20, c = tid - (tid / 20) * 20;
            hbt[r * 20 + c] = sigmoidf(pre[r * PSTR + i * HID + c]);
            asm volatile("bar.sync 1, 160;" ::: "memory");
            #pragma unroll
            for (int lv = 0; lv < 4; ++lv) {
                float acc = pre[((lv + 1) * MROWS + r) * PSTR + i * HID + c];
                const float* w  = wd + lv * 400 + c * 20;
                const float* hh = hbt + lv * 160 + r * 20;
                #pragma unroll
                for (int ci = 0; ci < 20; ++ci) acc = fmaf(w[ci], hh[ci], acc);
                hbt[(lv + 1) * 160 + r * 20 + c] = sigmoidf(acc);
                asm volatile("bar.sync 1, 160;" ::: "memory");
            }
            if (tid < MROWS) {          // fc6 diag + sample
                const int r_ = tid;
                float acc = pre6[r_ * P6STR + i];
                const float* w  = wd + 2000;
                const float* hh = hbt + 4 * 160 + r_ * 20;
                #pragma unroll
                for (int ci = 0; ci < 20; ++ci) acc = fmaf(w[ci], hh[ci], acc);
                float x = sigmoidf(acc);
                osm[r_ * NS + i] = x;
                scur[r_] = (x >= usm[r_ * NS + i]) ? 1.0f : -1.0f;
            }
        }
        __syncthreads();

        // ===== scatter (bulk, no internal barriers) =====
        if (i < 63) {
            const int nso1 = 63 - i;
            const int nt = nso1 * HID;
            const int tbase = (i + 1) * HID;
            const size_t soff = (size_t)slab_off1(i);

            // fc2..fc5
            #pragma unroll 1
            for (int l = 0; l < 4; ++l) {
                const float* wb = g_Ws4 + (size_t)l * LVL + soff * 400;
                float* prl = pre + (size_t)(l + 1) * MROWS * PSTR;
                ulonglong2 h0[5], h1[5];
                {
                    const ulonglong2* hp0 = (const ulonglong2*)(hbt + l * 160 + r0 * 20);
                    const ulonglong2* hp1 = (const ulonglong2*)(hbt + l * 160 + r1 * 20);
                    #pragma unroll
                    for (int k = 0; k < 5; ++k) { h0[k] = hp0[k]; h1[k] = hp1[k]; }
                }
                #pragma unroll 2
                for (int j = jj; j < nt; j += 160) {
                    ulonglong2 w[5];
                    #pragma unroll
                    for (int k = 0; k < 5; ++k)
                        w[k] = *(const ulonglong2*)(wb + ((size_t)k * nt + j) * 4);
                    float* d0p = prl + r0 * PSTR + tbase + j;
                    float* d1p = prl + r1 * PSTR + tbase + j;
                    unsigned long long a0 = pack2(*d0p, 0.0f);
                    unsigned long long a1 = pack2(*d1p, 0.0f);
                    #pragma unroll
                    for (int k = 0; k < 5; ++k) {
                        a0 = ffma2(w[k].x, h0[k].x, a0); a0 = ffma2(w[k].y, h0[k].y, a0);
                        a1 = ffma2(w[k].x, h1[k].x, a1); a1 = ffma2(w[k].y, h1[k].y, a1);
                    }
                    *d0p = hsum2(a0);
                    *d1p = hsum2(a1);
                }
            }
            // fc1 (rank-1)
            {
                const float* wb1 = g_W1s + soff * 20;
                float s0 = scur[0], s1 = scur[1], s2 = scur[2], s3 = scur[3];
                float s4 = scur[4], s5 = scur[5], s6 = scur[6], s7 = scur[7];
                float* p1 = pre + tbase;
                for (int j = tid; j < nt; j += T) {
                    float w = wb1[j];
                    p1[0 * PSTR + j] += w * s0;  p1[1 * PSTR + j] += w * s1;
                    p1[2 * PSTR + j] += w * s2;  p1[3 * PSTR + j] += w * s3;
                    p1[4 * PSTR + j] += w * s4;  p1[5 * PSTR + j] += w * s5;
                    p1[6 * PSTR + j] += w * s6;  p1[7 * PSTR + j] += w * s7;
                }
            }
            // fc6 (nso1 <= 63 targets: single round, lanes jj < nso1)
            if (jj < nso1) {
                const float* wb6 = g_W6s + soff * 20;
                ulonglong2 h0_[5], h1_[5];
                {
                    const ulonglong2* hp0 = (const ulonglong2*)(hbt + 4 * 160 + r0 * 20);
                    const ulonglong2* hp1 = (const ulonglong2*)(hbt + 4 * 160 + r1 * 20);
                    #pragma unroll
                    for (int k = 0; k < 5; ++k) { h0_[k] = hp0[k]; h1_[k] = hp1[k]; }
                }
                ulonglong2 w[5];
                #pragma unroll
                for (int k = 0; k < 5; ++k)
                    w[k] = *(const ulonglong2*)(wb6 + ((size_t)k * nso1 + jj) * 4);
                float* d0p = pre6 + r0 * P6STR + (i + 1 + jj);
                float* d1p = pre6 + r1 * P6STR + (i + 1 + jj);
                unsigned long long a0 = pack2(*d0p, 0.0f);
                unsigned long long a1 = pack2(*d1p, 0.0f);
                #pragma unroll
                for (int k = 0; k < 5; ++k) {
                    a0 = ffma2(w[k].x, h0_[k].x, a0); a0 = ffma2(w[k].y, h0_[k].y, a0);
                    a1 = ffma2(w[k].x, h1_[k].x, a1); a1 = ffma2(w[k].y, h1_[k].y, a1);
                }
                *d0p = hsum2(a0);
                *d1p = hsum2(a1);
            }
            // prefetch next step's diag weights
            {
                const float* src = g_Wd + (size_t)(i + 1) * 2020;
                for (int k = tid; k < 2020; k += T) wd[k] = src[k];
            }
        }
        __syncthreads();
    }

    if (tid < 512)
        out[(size_t)blockIdx.x * 512 + tid] = osm[tid];
}

extern "C" void kernel_launch(void* const* d_in, const int* in_sizes, int n_in,
                              void* d_out, int out_size)
{
    (void)in_sizes; (void)n_in; (void)out_size;
    const float* u  = (const float*)d_in[1];
    const float* W1 = (const float*)d_in[2];
    const float* W2 = (const float*)d_in[3];
    const float* W3 = (const float*)d_in[4];
    const float* W4 = (const float*)d_in[5];
    const float* W5 = (const float*)d_in[6];
    const float* W6 = (const float*)d_in[7];
    float* out = (float*)d_out;

    dim3 pg(64, 6);
    prep_scatter<<<pg, 256>>>(W1, W2, W3, W4, W5, W6);

    const int smem_bytes = (5 * MROWS * PSTR + MROWS * P6STR + 5 * 160
                            + 512 + 512 + 2020 + 8) * (int)sizeof(float);
    cudaFuncSetAttribute(net_kernel, cudaFuncAttributeMaxDynamicSharedMemorySize, smem_bytes);
    net_kernel<<<BATCH / MROWS, T, smem_bytes>>>(u, out);
}